// round 9
// baseline (speedup 1.0000x reference)
#include <cuda_runtime.h>

#define N 8192
#define D 256
#define NC 10
#define GRID 128
#define BLOCK 512
#define RPB (N / GRID)       // 64 rows per block
#define NSUB 8               // row sub-groups (one smem replica each)
#define RPT (RPB / NSUB)     // 8 rows per thread

#define SMEM_BYTES (NSUB * NC * D * 4)   // 80 KB dynamic

// PAR = COV * 0.5 / BATCH_SIZE = 0.5 / 8192
#define PARF 6.103515625e-05

// Global accumulators. Statically zero-initialized; the finishing block
// resets them after consuming, so every launch / graph replay sees zeros.
__device__ float4 g_v4[NC][D / 4];   // per-class column sums (float[NC][D])
__device__ float  g_S[NC];           // per-class scalar sum of squares
__device__ int    g_cnt[NC];
__device__ unsigned int g_done;

__device__ __forceinline__ void red_add_v4(float4* addr, float4 v) {
    asm volatile("red.global.add.v4.f32 [%0], {%1, %2, %3, %4};"
                 :: "l"(addr), "f"(v.x), "f"(v.y), "f"(v.z), "f"(v.w)
                 : "memory");
}

__global__ __launch_bounds__(BLOCK) void fused_kernel(const float* __restrict__ out,
                                                      const int* __restrict__ label,
                                                      float* __restrict__ res) {
    extern __shared__ float sv[];        // [NSUB][NC][D], 80 KB, race-free by construction
    __shared__ float  sS[NC];
    __shared__ int    s_lab[RPB];
    __shared__ int    scnt[NC];
    __shared__ int    s_last;
    __shared__ double red[BLOCK];
    __shared__ double red2[BLOCK];
    __shared__ double s_xx0, s_xxL;

    int t   = threadIdx.x;
    int cg  = t & 63;      // column group: owns cols 4*cg .. 4*cg+3
    int sub = t >> 6;      // row sub-group 0..7 (warp-pair-uniform)
    int r0  = blockIdx.x * RPB;

    // Zero the replica accumulators: 5120 float4s across 512 threads.
    float4* svz = (float4*)sv;
    #pragma unroll
    for (int i = 0; i < NSUB * NC * D / 4 / BLOCK; i++)
        svz[t + i * BLOCK] = make_float4(0.f, 0.f, 0.f, 0.f);
    if (t < NC) { sS[t] = 0.f; scnt[t] = 0; }
    if (t < RPB) s_lab[t] = label[r0 + t];
    __syncthreads();

    if (t < RPB) atomicAdd(&scnt[s_lab[t]], 1);

    // ---- prefetch: 8 rows per thread, 4 columns each (max MLP) ----
    const float4* src = (const float4*)out;   // row stride D/4 = 64
    int rbase = r0 + sub * RPT;
    float4 x[RPT];
    int    lab[RPT];
    #pragma unroll
    for (int i = 0; i < RPT; i++) lab[i] = s_lab[sub * RPT + i];
    #pragma unroll
    for (int i = 0; i < RPT; i++)
        x[i] = src[(size_t)(rbase + i) * (D / 4) + cg];

    // ---- smem RMW into this subgroup's private replica (no races) ----
    #pragma unroll
    for (int i = 0; i < RPT; i++) {
        float4* slot = (float4*)&sv[((sub * NC) + lab[i]) * D + 4 * cg];
        float4 a = *slot;
        a.x += x[i].x; a.y += x[i].y; a.z += x[i].z; a.w += x[i].w;
        *slot = a;
    }

    // ---- per-class sum of squares: per-row warp-reduce + one ATOMS ----
    #pragma unroll
    for (int i = 0; i < RPT; i++) {
        float ss = x[i].x * x[i].x + x[i].y * x[i].y
                 + x[i].z * x[i].z + x[i].w * x[i].w;
        #pragma unroll
        for (int o = 16; o; o >>= 1) ss += __shfl_xor_sync(0xffffffffu, ss, o);
        if ((t & 31) == 0) atomicAdd(&sS[lab[i]], ss);   // l warp-uniform
    }
    __syncthreads();

    // ---- flush: 640 (class, cg) slots; combine 8 replicas + one v4 RED ----
    for (int idx = t; idx < NC * 64; idx += BLOCK) {
        int c = idx >> 6, g = idx & 63;
        float4 s = make_float4(0.f, 0.f, 0.f, 0.f);
        #pragma unroll
        for (int r = 0; r < NSUB; r++) {
            float4 a = *(float4*)&sv[((r * NC) + c) * D + 4 * g];
            s.x += a.x; s.y += a.y; s.z += a.z; s.w += a.w;
        }
        red_add_v4(&g_v4[c][g], s);
    }
    if (t < NC) {
        if (scnt[t]) atomicAdd(&g_cnt[t], scnt[t]);
        atomicAdd(&g_S[t], sS[t]);
    }

    // ---- last-block-arrival handoff ----
    __threadfence();
    __syncthreads();
    if (t == 0) s_last = (atomicAdd(&g_done, 1u) == GRID - 1);
    __syncthreads();
    if (!s_last) return;

    // =================== finish phase (one block) ===================
    __threadfence();   // acquire side of the counter handshake

    __shared__ int   cnt[NC];
    __shared__ float Sc[NC];
    if (t < NC) { cnt[t] = g_cnt[t]; g_cnt[t] = 0;
                  Sc[t]  = g_S[t];   g_S[t]  = 0.f; }
    if (t == 0) g_done = 0;

    int l0 = label[0];
    int lL = label[N - 1];
    // Row set A = [0, N-1) excludes row N-1; B = [1, N) excludes row 0.
    int   tc = t & (D - 1);                    // column index 0..255 (threads 256.. mirror)
    float x0 = out[tc];                        // row 0,   column tc
    float xL = out[(size_t)(N - 1) * D + tc];  // row N-1, column tc

    // ||x0||^2 and ||xL||^2 (each column counted once: only t < D contributes)
    red[t]  = (t < D) ? (double)x0 * (double)x0 : 0.0;
    red2[t] = (t < D) ? (double)xL * (double)xL : 0.0;
    __syncthreads();
    #pragma unroll
    for (int s = BLOCK / 2; s > 0; s >>= 1) {
        if (t < s) { red[t] += red[t + s]; red2[t] += red2[t + s]; }
        __syncthreads();
    }
    if (t == 0) { s_xx0 = red[0]; s_xxL = red2[0]; }
    __syncthreads();

    // Per-column:  -4 * sum_c vA_c[t]*vB_c[t]  +  2 * uA[t]*uB[t]
    // Split the 10-class loop across the two half-blocks: threads t<256 do
    // classes 0..4, threads 256.. do classes 5..9 (same column tc).
    float* gv = (float*)g_v4;     // [NC][D]
    double p = 0.0;
    float uAt = 0.f, uBt = 0.f;
    int cbase = (t < D) ? 0 : 5;
    #pragma unroll
    for (int k = 0; k < 5; k++) {
        int c = cbase + k;
        float v = gv[c * D + tc];
        gv[c * D + tc] = 0.f;      // consume + reset (sole reader/writer)
        float vA = v - ((lL == c) ? xL : 0.f);
        float vB = v - ((l0 == c) ? x0 : 0.f);
        p -= 4.0 * (double)vA * (double)vB;
        uAt += vA; uBt += vB;
    }
    // uA[t]*uB[t] needs the full 10-class sums per column: exchange halves.
    red[t]  = (double)uAt;
    red2[t] = (double)uBt;
    __syncthreads();
    {
        int o = (t < D) ? t + D : t - D;       // partner thread (other class half)
        float uA_full = uAt + (float)red[o];
        float uB_full = uBt + (float)red2[o];
        if (t < D) p += 2.0 * (double)uA_full * (double)uB_full;
    }

    // Scalar part: 2*sum_c [nB*SA_c + nA*SB_c]  -  (N-1)*(SA + SB)
    if (t == 0) {
        double sc = 0.0, SA = 0.0, SB = 0.0;
        #pragma unroll
        for (int c = 0; c < NC; c++) {
            double S   = (double)Sc[c];
            double SAc = S - ((lL == c) ? s_xxL : 0.0);
            double SBc = S - ((l0 == c) ? s_xx0 : 0.0);
            double nA  = (double)(cnt[c] - (lL == c));
            double nB  = (double)(cnt[c] - (l0 == c));
            sc += 2.0 * (nB * SAc + nA * SBc);
            SA += SAc; SB += SBc;
        }
        sc -= (double)(N - 1) * (SA + SB);
        p += sc;
    }
    __syncthreads();   // reuse of red[] below

    red[t] = p;
    __syncthreads();
    #pragma unroll
    for (int s = BLOCK / 2; s > 0; s >>= 1) {
        if (t < s) red[t] += red[t + s];
        __syncthreads();
    }
    if (t == 0) res[0] = (float)(PARF * red[0]);
}

extern "C" void kernel_launch(void* const* d_in, const int* in_sizes, int n_in,
                              void* d_out, int out_size) {
    const float* out   = (const float*)d_in[0];
    const int*   label = (const int*)d_in[1];
    cudaFuncSetAttribute(fused_kernel,
                         cudaFuncAttributeMaxDynamicSharedMemorySize, SMEM_BYTES);
    fused_kernel<<<GRID, BLOCK, SMEM_BYTES>>>(out, label, (float*)d_out);
}

// round 11
// speedup vs baseline: 1.1557x; 1.1557x over previous
#include <cuda_runtime.h>

#define N 8192
#define D 256
#define NC 10
#define GRID 128
#define BLOCK 256
#define RPB (N / GRID)       // 64 rows per block
#define NSUB 4               // row sub-groups (64 threads each, private replica)
#define RPT (RPB / NSUB)     // 16 rows per thread

// PAR = COV * 0.5 / BATCH_SIZE = 0.5 / 8192
#define PARF 6.103515625e-05

// Global accumulators. Statically zero-initialized; the finishing block
// resets them after consuming, so every launch / graph replay sees zeros.
__device__ float4 g_v4[NC][D / 4];   // per-class column sums (float[NC][D])
__device__ float  g_S[NC];           // per-class scalar sum of squares
__device__ int    g_cnt[NC];
__device__ unsigned int g_done;

__device__ __forceinline__ void red_add_v4(float4* addr, float4 v) {
    asm volatile("red.global.add.v4.f32 [%0], {%1, %2, %3, %4};"
                 :: "l"(addr), "f"(v.x), "f"(v.y), "f"(v.z), "f"(v.w)
                 : "memory");
}

__global__ __launch_bounds__(BLOCK) void fused_kernel(const float* __restrict__ out,
                                                      const int* __restrict__ label,
                                                      float* __restrict__ res) {
    __shared__ float  sv[NSUB][NC][D];   // 40 KB: per-replica per-class column sums
    __shared__ float  sS[NC];
    __shared__ int    s_lab[RPB];
    __shared__ int    scnt[NC];
    __shared__ int    s_last;
    __shared__ double red[BLOCK];        // 2 KB

    int t   = threadIdx.x;
    int cg  = t & 63;      // column group: owns cols 4*cg .. 4*cg+3
    int sub = t >> 6;      // row sub-group 0..3 (private smem replica -> race-free)
    int r0  = blockIdx.x * RPB;

    // Zero replica accumulators: 2560 float4s / 256 threads = 10 STS.128 each.
    float4* svz = (float4*)sv;
    #pragma unroll
    for (int i = 0; i < NSUB * NC * D / 4 / BLOCK; i++)
        svz[t + i * BLOCK] = make_float4(0.f, 0.f, 0.f, 0.f);
    if (t < NC) { sS[t] = 0.f; scnt[t] = 0; }
    if (t < RPB) s_lab[t] = label[r0 + t];
    __syncthreads();

    if (t < RPB) atomicAdd(&scnt[s_lab[t]], 1);

    // ---- mainloop: 16 rows per thread, float4 per row ----
    const float4* src = (const float4*)out;   // row stride D/4 = 64
    int rbase = r0 + sub * RPT;

    #pragma unroll
    for (int i = 0; i < RPT; i++) {
        float4 x = src[(size_t)(rbase + i) * (D / 4) + cg];
        int l = s_lab[sub * RPT + i];          // warp-uniform

        // column-sum RMW into this subgroup's private replica
        float4* slot = (float4*)&sv[sub][l][4 * cg];
        float4 a = *slot;
        a.x += x.x; a.y += x.y; a.z += x.z; a.w += x.w;
        *slot = a;

        // per-class sum of squares: warp shuffle-reduce + one ATOMS per warp
        float ss = x.x * x.x + x.y * x.y + x.z * x.z + x.w * x.w;
        #pragma unroll
        for (int o = 16; o; o >>= 1) ss += __shfl_xor_sync(0xffffffffu, ss, o);
        if ((t & 31) == 0) atomicAdd(&sS[l], ss);
    }
    __syncthreads();

    // ---- flush: 640 (class, colgroup) slots across 256 threads ----
    for (int idx = t; idx < NC * 64; idx += BLOCK) {
        int c = idx >> 6, g = idx & 63;
        float4 a = *(float4*)&sv[0][c][4 * g];
        float4 b = *(float4*)&sv[1][c][4 * g];
        float4 d = *(float4*)&sv[2][c][4 * g];
        float4 e = *(float4*)&sv[3][c][4 * g];
        red_add_v4(&g_v4[c][g],
                   make_float4(a.x + b.x + d.x + e.x,
                               a.y + b.y + d.y + e.y,
                               a.z + b.z + d.z + e.z,
                               a.w + b.w + d.w + e.w));
    }
    if (t < NC) {
        if (scnt[t]) atomicAdd(&g_cnt[t], scnt[t]);
        atomicAdd(&g_S[t], sS[t]);
    }

    // ---- last-block-arrival handoff ----
    __threadfence();
    __syncthreads();
    if (t == 0) s_last = (atomicAdd(&g_done, 1u) == GRID - 1);
    __syncthreads();
    if (!s_last) return;

    // =================== finish phase (one block, ONE reduction) ===========
    __threadfence();   // acquire side of the counter handshake

    __shared__ int cnt[NC];
    if (t < NC) { cnt[t] = g_cnt[t]; g_cnt[t] = 0; }
    if (t == 0) g_done = 0;
    __syncthreads();

    int l0 = label[0];
    int lL = label[N - 1];
    // Row set A = [0, N-1) excludes row N-1; B = [1, N) excludes row 0.
    float x0 = out[t];                        // row 0,   column t
    float xL = out[(size_t)(N - 1) * D + t];  // row N-1, column t

    // Per-column quadratic part:  -4*sum_c vA_c[t]*vB_c[t]  +  2*uA[t]*uB[t]
    float* gv = (float*)g_v4;     // [NC][D]
    double p = 0.0;
    float uAt = 0.f, uBt = 0.f;
    #pragma unroll
    for (int c = 0; c < NC; c++) {
        float v = gv[c * D + t];
        gv[c * D + t] = 0.f;       // consume + reset (sole reader/writer)
        float vA = v - ((lL == c) ? xL : 0.f);
        float vB = v - ((l0 == c) ? x0 : 0.f);
        p -= 4.0 * (double)vA * (double)vB;
        uAt += vA; uBt += vB;
    }
    p += 2.0 * (double)uAt * (double)uBt;

    // Folded scalar corrections, distributed per column:
    //   column t adds (N-1-2*nB_{lL})*xL[t]^2 + (N-1-2*nA_{l0})*x0[t]^2
    // where nA_c = cnt_c - [c==lL],  nB_c = cnt_c - [c==l0].
    {
        double wL = (double)(N - 1) - 2.0 * (double)(cnt[lL] - (l0 == lL));
        double w0 = (double)(N - 1) - 2.0 * (double)(cnt[l0] - (lL == l0));
        p += wL * (double)xL * (double)xL + w0 * (double)x0 * (double)x0;
    }

    // Pure-S_c scalar part on thread 0:  2*sum_c (nA_c + nB_c - (N-1)) * S_c
    if (t == 0) {
        double sc = 0.0;
        #pragma unroll
        for (int c = 0; c < NC; c++) {
            double S  = (double)g_S[c];
            g_S[c] = 0.f;
            double nA = (double)(cnt[c] - (lL == c));
            double nB = (double)(cnt[c] - (l0 == c));
            sc += (nA + nB - (double)(N - 1)) * S;
        }
        p += 2.0 * sc;
    }

    red[t] = p;
    __syncthreads();
    #pragma unroll
    for (int s = BLOCK / 2; s > 0; s >>= 1) {
        if (t < s) red[t] += red[t + s];
        __syncthreads();
    }
    if (t == 0) res[0] = (float)(PARF * red[0]);
}

extern "C" void kernel_launch(void* const* d_in, const int* in_sizes, int n_in,
                              void* d_out, int out_size) {
    const float* out   = (const float*)d_in[0];
    const int*   label = (const int*)d_in[1];
    fused_kernel<<<GRID, BLOCK>>>(out, label, (float*)d_out);
}